// round 10
// baseline (speedup 1.0000x reference)
#include <cuda_runtime.h>
#include <cstdint>

// GlobalAttentionModule_7438883356930
//
// Identity: softmax row-sums are 1 and v is constant along the softmaxed axis,
// so out = relu(GroupNorm_32(Wv @ feat + bv)). (Verified: rel_err ~1e-7.)
//
// R8: single-wave layout. grid=128 (cluster of 2 = one (batch,group) split in
// two N-halves), 256 threads/block. Each thread: 4ch x 4n register tile over a
// 32-k quarter, feat read directly via LDG.128 (16x register reuse, L2-shared
// across the 64 blocks per batch). k-quarters combined in smem, GN stats
// across the half-pair via DSMEM. Critical path ~3.7k cyc, one wave.

#define C_DIM    128
#define N_DIM    512
#define B_DIM    2
#define GROUPS   32
#define CPG      4
#define HALVES   2                     // cluster size: N split in halves
#define HALF_N   (N_DIM / HALVES)      // 256
#define NF4      (HALF_N / 4)          // 64 float4 positions per block
#define KSPLIT   4
#define KPART    (C_DIM / KSPLIT)      // 32
#define THREADS  256                   // KSPLIT * NF4
#define EPS      1e-5f

__device__ __forceinline__ uint32_t smem_u32(const void* p) {
    return (uint32_t)__cvta_generic_to_shared(p);
}

__global__ __launch_bounds__(THREADS) __cluster_dims__(HALVES, 1, 1)
void fused_onewave(const float* __restrict__ feat,   // [B, C, N]
                   const float* __restrict__ Wv,     // [C, C]
                   const float* __restrict__ bv,     // [C]
                   const float* __restrict__ gamma,  // [C]
                   const float* __restrict__ beta,   // [C]
                   float* __restrict__ out)          // [B, C, N]
{
    const int bg   = blockIdx.x / HALVES;    // (batch, group)
    const int half = blockIdx.x % HALVES;    // cluster rank
    const int b    = bg / GROUPS;
    const int g    = bg % GROUPS;
    const int t    = threadIdx.x;

    __shared__ float  w[CPG][C_DIM];                       // 2 KB
    __shared__ float4 scomb[KSPLIT - 1][CPG][NF4];         // 12 KB quad partials
    __shared__ float  red_s[2], red_ss[2];
    __shared__ float2 part;                                // DSMEM-visible
    __shared__ float  s_mean, s_rstd;

    const int q = t >> 6;          // k-quarter 0..3
    const int j = t & 63;          // float4 n index 0..63

    // ---- stage weights (512 floats) ----
    {
        const float* wsrc = Wv + (size_t)(g * CPG) * C_DIM;
        #pragma unroll
        for (int i = t; i < CPG * C_DIM; i += THREADS)
            w[i / C_DIM][i % C_DIM] = wsrc[i];
    }
    __syncthreads();

    // ---- GEMM: 4ch x 4n register tile, k in [q*32, q*32+32), feat via LDG ----
    float4 a0 = make_float4(0.f, 0.f, 0.f, 0.f);
    float4 a1 = a0, a2 = a0, a3 = a0;
    {
        const float* fb = feat + (size_t)b * C_DIM * N_DIM
                        + (size_t)(q * KPART) * N_DIM + half * HALF_N + 4 * j;
        const int k0 = q * KPART;
        #pragma unroll 8
        for (int kk = 0; kk < KPART; kk++) {
            const float4 x = *reinterpret_cast<const float4*>(fb + (size_t)kk * N_DIM);
            const int k = k0 + kk;
            const float w0 = w[0][k], w1 = w[1][k], w2 = w[2][k], w3 = w[3][k];
            a0.x = fmaf(w0, x.x, a0.x); a0.y = fmaf(w0, x.y, a0.y);
            a0.z = fmaf(w0, x.z, a0.z); a0.w = fmaf(w0, x.w, a0.w);
            a1.x = fmaf(w1, x.x, a1.x); a1.y = fmaf(w1, x.y, a1.y);
            a1.z = fmaf(w1, x.z, a1.z); a1.w = fmaf(w1, x.w, a1.w);
            a2.x = fmaf(w2, x.x, a2.x); a2.y = fmaf(w2, x.y, a2.y);
            a2.z = fmaf(w2, x.z, a2.z); a2.w = fmaf(w2, x.w, a2.w);
            a3.x = fmaf(w3, x.x, a3.x); a3.y = fmaf(w3, x.y, a3.y);
            a3.z = fmaf(w3, x.z, a3.z); a3.w = fmaf(w3, x.w, a3.w);
        }
    }

    // ---- deterministic k-quad combine: quads 1..3 -> smem, quad 0 folds ----
    if (q > 0) {
        scomb[q - 1][0][j] = a0;
        scomb[q - 1][1][j] = a1;
        scomb[q - 1][2][j] = a2;
        scomb[q - 1][3][j] = a3;
    }
    __syncthreads();

    float ga0 = 0.f, ga1 = 0.f, ga2 = 0.f, ga3 = 0.f;
    float be0 = 0.f, be1 = 0.f, be2 = 0.f, be3 = 0.f;

    if (q == 0) {
        #pragma unroll
        for (int r = 0; r < KSPLIT - 1; r++) {
            float4 p;
            p = scomb[r][0][j]; a0.x += p.x; a0.y += p.y; a0.z += p.z; a0.w += p.w;
            p = scomb[r][1][j]; a1.x += p.x; a1.y += p.y; a1.z += p.z; a1.w += p.w;
            p = scomb[r][2][j]; a2.x += p.x; a2.y += p.y; a2.z += p.z; a2.w += p.w;
            p = scomb[r][3][j]; a3.x += p.x; a3.y += p.y; a3.z += p.z; a3.w += p.w;
        }
        const int c0 = g * CPG;
        const float b0 = bv[c0 + 0], b1 = bv[c0 + 1], b2 = bv[c0 + 2], b3 = bv[c0 + 3];
        a0.x += b0; a0.y += b0; a0.z += b0; a0.w += b0;
        a1.x += b1; a1.y += b1; a1.z += b1; a1.w += b1;
        a2.x += b2; a2.y += b2; a2.z += b2; a2.w += b2;
        a3.x += b3; a3.y += b3; a3.z += b3; a3.w += b3;

        // prefetch affine params (latency hides under stats + cluster barrier)
        ga0 = gamma[c0 + 0]; ga1 = gamma[c0 + 1]; ga2 = gamma[c0 + 2]; ga3 = gamma[c0 + 3];
        be0 = beta[c0 + 0];  be1 = beta[c0 + 1];  be2 = beta[c0 + 2];  be3 = beta[c0 + 3];

        // partial stats over this block's 4ch x 256n values (warps 0..1)
        float s  = (a0.x + a0.y + a0.z + a0.w) + (a1.x + a1.y + a1.z + a1.w)
                 + (a2.x + a2.y + a2.z + a2.w) + (a3.x + a3.y + a3.z + a3.w);
        float ss = (a0.x * a0.x + a0.y * a0.y + a0.z * a0.z + a0.w * a0.w)
                 + (a1.x * a1.x + a1.y * a1.y + a1.z * a1.z + a1.w * a1.w)
                 + (a2.x * a2.x + a2.y * a2.y + a2.z * a2.z + a2.w * a2.w)
                 + (a3.x * a3.x + a3.y * a3.y + a3.z * a3.z + a3.w * a3.w);
        #pragma unroll
        for (int o = 16; o > 0; o >>= 1) {
            s  += __shfl_xor_sync(0xffffffffu, s,  o);
            ss += __shfl_xor_sync(0xffffffffu, ss, o);
        }
        const int warp = t >> 5, lane = t & 31;    // 0 or 1
        if (lane == 0) { red_s[warp] = s; red_ss[warp] = ss; }
    }
    __syncthreads();
    if (t == 0) part = make_float2(red_s[0] + red_s[1], red_ss[0] + red_ss[1]);

    // ---- cluster barrier 1: both halves' `part` published ----
    asm volatile("barrier.cluster.arrive.aligned;" ::: "memory");
    asm volatile("barrier.cluster.wait.aligned;"   ::: "memory");

    // ---- fold 2 peer partials via DSMEM (deterministic) ----
    if (t == 0) {
        float fs = 0.f, fss = 0.f;
        const uint32_t local = smem_u32(&part);
        #pragma unroll
        for (int r = 0; r < HALVES; r++) {
            uint32_t remote;
            asm("mapa.shared::cluster.u32 %0, %1, %2;"
                : "=r"(remote) : "r"(local), "r"(r));
            float px, py;
            asm volatile("ld.shared::cluster.v2.f32 {%0, %1}, [%2];"
                         : "=f"(px), "=f"(py) : "r"(remote));
            fs += px; fss += py;
        }
        const float inv = 1.0f / (float)(CPG * N_DIM);
        const float m   = fs * inv;
        const float var = fss * inv - m * m;
        s_mean = m;
        s_rstd = rsqrtf(var + EPS);
    }

    // ---- cluster barrier 2: DSMEM reads done (safe to exit after) ----
    asm volatile("barrier.cluster.arrive.aligned;" ::: "memory");
    asm volatile("barrier.cluster.wait.aligned;"   ::: "memory");
    __syncthreads();

    // ---- normalize + affine + relu + store (quad-0 threads hold v) ----
    if (q == 0) {
        const float m = s_mean, r = s_rstd;
        const int c0 = g * CPG;
        const int n0 = half * HALF_N + 4 * j;
        float* ob = out + ((size_t)b * C_DIM + c0) * N_DIM + n0;

        const float g0 = ga0 * r, g1 = ga1 * r, g2 = ga2 * r, g3 = ga3 * r;
        float4 o4;
        o4.x = fmaxf(fmaf(a0.x - m, g0, be0), 0.f);
        o4.y = fmaxf(fmaf(a0.y - m, g0, be0), 0.f);
        o4.z = fmaxf(fmaf(a0.z - m, g0, be0), 0.f);
        o4.w = fmaxf(fmaf(a0.w - m, g0, be0), 0.f);
        *reinterpret_cast<float4*>(ob + 0 * N_DIM) = o4;
        o4.x = fmaxf(fmaf(a1.x - m, g1, be1), 0.f);
        o4.y = fmaxf(fmaf(a1.y - m, g1, be1), 0.f);
        o4.z = fmaxf(fmaf(a1.z - m, g1, be1), 0.f);
        o4.w = fmaxf(fmaf(a1.w - m, g1, be1), 0.f);
        *reinterpret_cast<float4*>(ob + 1 * N_DIM) = o4;
        o4.x = fmaxf(fmaf(a2.x - m, g2, be2), 0.f);
        o4.y = fmaxf(fmaf(a2.y - m, g2, be2), 0.f);
        o4.z = fmaxf(fmaf(a2.z - m, g2, be2), 0.f);
        o4.w = fmaxf(fmaf(a2.w - m, g2, be2), 0.f);
        *reinterpret_cast<float4*>(ob + 2 * N_DIM) = o4;
        o4.x = fmaxf(fmaf(a3.x - m, g3, be3), 0.f);
        o4.y = fmaxf(fmaf(a3.y - m, g3, be3), 0.f);
        o4.z = fmaxf(fmaf(a3.z - m, g3, be3), 0.f);
        o4.w = fmaxf(fmaf(a3.w - m, g3, be3), 0.f);
        *reinterpret_cast<float4*>(ob + 3 * N_DIM) = o4;
    }
}

extern "C" void kernel_launch(void* const* d_in, const int* in_sizes, int n_in,
                              void* d_out, int out_size)
{
    // 0 feat, 1 Wk, 2 bk, 3 Wq, 4 bq, 5 Wv, 6 bv, 7 gn_v_g, 8 gn_v_b, ...
    const float* feat = (const float*)d_in[0];
    const float* Wv   = (const float*)d_in[5];
    const float* bv   = (const float*)d_in[6];
    const float* gn_g = (const float*)d_in[7];
    const float* gn_b = (const float*)d_in[8];
    float* out = (float*)d_out;

    fused_onewave<<<B_DIM * GROUPS * HALVES, THREADS>>>(feat, Wv, bv, gn_g, gn_b, out);
}

// round 11
// speedup vs baseline: 1.7610x; 1.7610x over previous
#include <cuda_runtime.h>
#include <cstdint>

// GlobalAttentionModule_7438883356930
//
// Identity: softmax row-sums are 1 and v is constant along the softmaxed axis,
// so out = relu(GroupNorm_32(Wv @ feat + bv)). (Verified: rel_err ~1e-7.)
//
// R10: one wave (grid=128, cluster-2 per (b,g), 148=2*74 packs) AND 16 warps/SM
// (512 threads). k split 8 ways; mainloop = LDG.128(feat) + LDS.128(wT) +
// 16 FMA per iter, fully unrolled (high MLP). 8 k-slices folded by 256
// epilogue threads; GN stats across the half-pair via DSMEM (validated R8).

#define C_DIM    128
#define N_DIM    512
#define B_DIM    2
#define GROUPS   32
#define CPG      4
#define HALVES   2                     // cluster size
#define HALF_N   (N_DIM / HALVES)      // 256
#define NF4      (HALF_N / 4)          // 64 float4 n-positions
#define KSPLIT   8
#define KPART    (C_DIM / KSPLIT)      // 16
#define THREADS  (KSPLIT * NF4)        // 512
#define EPS      1e-5f

__device__ __forceinline__ uint32_t smem_u32(const void* p) {
    return (uint32_t)__cvta_generic_to_shared(p);
}

__global__ __launch_bounds__(THREADS) __cluster_dims__(HALVES, 1, 1)
void fused_onewave(const float* __restrict__ feat,   // [B, C, N]
                   const float* __restrict__ Wv,     // [C, C]
                   const float* __restrict__ bv,     // [C]
                   const float* __restrict__ gamma,  // [C]
                   const float* __restrict__ beta,   // [C]
                   float* __restrict__ out)          // [B, C, N]
{
    const int bg   = blockIdx.x / HALVES;    // (batch, group)
    const int half = blockIdx.x % HALVES;    // cluster rank
    const int b    = bg / GROUPS;
    const int g    = bg % GROUPS;
    const int t    = threadIdx.x;

    __shared__ float4 wT[C_DIM];                    // 2 KB: wT[k] = {w_c0..w_c3}[k]
    __shared__ float4 scomb[KSPLIT][CPG][NF4];      // 32 KB k-slice partials
    __shared__ float  red_s[8], red_ss[8];
    __shared__ float2 part;                         // DSMEM-visible (sum, sumsq)
    __shared__ float  s_mean, s_rstd;

    const int q = t >> 6;          // k-slice 0..7
    const int j = t & 63;          // float4 n index 0..63

    // ---- stage weights transposed: wT[k].{x,y,z,w} = Wv[g*4 + cc][k] ----
    {
        const int k  = t & 127;
        const int cc = t >> 7;     // 0..3
        reinterpret_cast<float*>(&wT[k])[cc] = Wv[(size_t)(g * CPG + cc) * C_DIM + k];
    }
    __syncthreads();

    // ---- GEMM: 4ch x 4n tile, k in [q*16, q*16+16), feat via LDG.128 ----
    float4 a0 = make_float4(0.f, 0.f, 0.f, 0.f);
    float4 a1 = a0, a2 = a0, a3 = a0;
    {
        const float* fb = feat + (size_t)b * C_DIM * N_DIM
                        + (size_t)(q * KPART) * N_DIM + half * HALF_N + 4 * j;
        #pragma unroll
        for (int kk = 0; kk < KPART; kk++) {
            const float4 x  = *reinterpret_cast<const float4*>(fb + (size_t)kk * N_DIM);
            const float4 wv = wT[q * KPART + kk];
            a0.x = fmaf(wv.x, x.x, a0.x); a0.y = fmaf(wv.x, x.y, a0.y);
            a0.z = fmaf(wv.x, x.z, a0.z); a0.w = fmaf(wv.x, x.w, a0.w);
            a1.x = fmaf(wv.y, x.x, a1.x); a1.y = fmaf(wv.y, x.y, a1.y);
            a1.z = fmaf(wv.y, x.z, a1.z); a1.w = fmaf(wv.y, x.w, a1.w);
            a2.x = fmaf(wv.z, x.x, a2.x); a2.y = fmaf(wv.z, x.y, a2.y);
            a2.z = fmaf(wv.z, x.z, a2.z); a2.w = fmaf(wv.z, x.w, a2.w);
            a3.x = fmaf(wv.w, x.x, a3.x); a3.y = fmaf(wv.w, x.y, a3.y);
            a3.z = fmaf(wv.w, x.z, a3.z); a3.w = fmaf(wv.w, x.w, a3.w);
        }
    }

    // ---- publish all k-slice partials ----
    scomb[q][0][j] = a0;
    scomb[q][1][j] = a1;
    scomb[q][2][j] = a2;
    scomb[q][3][j] = a3;
    __syncthreads();

    // ---- fold by 256 epilogue threads (8 warps): thread -> (cc, j) ----
    const int ecc = t >> 6;        // 0..3 for t<256
    const int ej  = t & 63;
    float4 v = make_float4(0.f, 0.f, 0.f, 0.f);
    float ga_raw = 0.f, be = 0.f;

    if (t < 256) {
        #pragma unroll
        for (int r = 0; r < KSPLIT; r++) {
            const float4 p = scomb[r][ecc][ej];
            v.x += p.x; v.y += p.y; v.z += p.z; v.w += p.w;
        }
        const int c  = g * CPG + ecc;
        const float bb = bv[c];
        v.x += bb; v.y += bb; v.z += bb; v.w += bb;

        // prefetch affine params (latency hides under stats + cluster barrier)
        ga_raw = gamma[c];
        be     = beta[c];

        // partial stats over this half-group (4ch x 256n)
        float s  = v.x + v.y + v.z + v.w;
        float ss = v.x * v.x + v.y * v.y + v.z * v.z + v.w * v.w;
        #pragma unroll
        for (int o = 16; o > 0; o >>= 1) {
            s  += __shfl_xor_sync(0xffffffffu, s,  o);
            ss += __shfl_xor_sync(0xffffffffu, ss, o);
        }
        const int warp = t >> 5, lane = t & 31;     // warps 0..7
        if (lane == 0) { red_s[warp] = s; red_ss[warp] = ss; }
    }
    __syncthreads();
    if (t == 0) {
        float ts = 0.f, tss = 0.f;
        #pragma unroll
        for (int i = 0; i < 8; i++) { ts += red_s[i]; tss += red_ss[i]; }
        part = make_float2(ts, tss);
    }

    // ---- cluster barrier 1: both halves' `part` published ----
    asm volatile("barrier.cluster.arrive.aligned;" ::: "memory");
    asm volatile("barrier.cluster.wait.aligned;"   ::: "memory");

    // ---- fold 2 peer partials via DSMEM (deterministic) ----
    if (t == 0) {
        float fs = 0.f, fss = 0.f;
        const uint32_t local = smem_u32(&part);
        #pragma unroll
        for (int r = 0; r < HALVES; r++) {
            uint32_t remote;
            asm("mapa.shared::cluster.u32 %0, %1, %2;"
                : "=r"(remote) : "r"(local), "r"(r));
            float px, py;
            asm volatile("ld.shared::cluster.v2.f32 {%0, %1}, [%2];"
                         : "=f"(px), "=f"(py) : "r"(remote));
            fs += px; fss += py;
        }
        const float inv = 1.0f / (float)(CPG * N_DIM);
        const float m   = fs * inv;
        const float var = fss * inv - m * m;
        s_mean = m;
        s_rstd = rsqrtf(var + EPS);
    }

    // ---- cluster barrier 2: DSMEM reads done (safe to exit after) ----
    asm volatile("barrier.cluster.arrive.aligned;" ::: "memory");
    asm volatile("barrier.cluster.wait.aligned;"   ::: "memory");
    __syncthreads();

    // ---- normalize + affine + relu + store (256 epilogue threads) ----
    if (t < 256) {
        const float m  = s_mean;
        const float ga = ga_raw * s_rstd;
        const int  c   = g * CPG + ecc;
        const int  n0  = half * HALF_N + 4 * ej;

        float4 o4;
        o4.x = fmaxf(fmaf(v.x - m, ga, be), 0.f);
        o4.y = fmaxf(fmaf(v.y - m, ga, be), 0.f);
        o4.z = fmaxf(fmaf(v.z - m, ga, be), 0.f);
        o4.w = fmaxf(fmaf(v.w - m, ga, be), 0.f);
        *reinterpret_cast<float4*>(out + ((size_t)b * C_DIM + c) * N_DIM + n0) = o4;
    }
}

extern "C" void kernel_launch(void* const* d_in, const int* in_sizes, int n_in,
                              void* d_out, int out_size)
{
    // 0 feat, 1 Wk, 2 bk, 3 Wq, 4 bq, 5 Wv, 6 bv, 7 gn_v_g, 8 gn_v_b, ...
    const float* feat = (const float*)d_in[0];
    const float* Wv   = (const float*)d_in[5];
    const float* bv   = (const float*)d_in[6];
    const float* gn_g = (const float*)d_in[7];
    const float* gn_b = (const float*)d_in[8];
    float* out = (float*)d_out;

    fused_onewave<<<B_DIM * GROUPS * HALVES, THREADS>>>(feat, Wv, bv, gn_g, gn_b, out);
}